// round 3
// baseline (speedup 1.0000x reference)
#include <cuda_runtime.h>
#include <math.h>

#define H 2048
#define N 16384
#define D 1024
#define EPSV 1e-8f
#define DIMSZ (5 + 3*D)   // 3077

// ---- scratch (__device__ globals; no allocs allowed) ----
__device__ float g_dim5[5];          // beta, gamma, shift logits
__device__ float g_k[D];
__device__ float g_erase[D];
__device__ float g_add[D];
__device__ float g_s[N];             // exp(beta*sim)  (no max-sub; bounded)
__device__ float g_gate[N];
__device__ float g_wp[N];            // unnormalized w_tilde^gamma
__device__ float g_pp[64];           // per-block pow-sum partials (deterministic)

__device__ __forceinline__ float warp_sum(float v) {
#pragma unroll
    for (int o = 16; o; o >>= 1) v += __shfl_xor_sync(0xffffffffu, v, o);
    return v;
}

// ---------------------------------------------------------------------------
// dim_out = W_dim @ hidden + b_dim, scattered into g_dim5/g_k/g_erase/g_add.
// Also zeroes the memory_read region of d_out (blocks row<D).
// <<<DIMSZ, 256>>>
// ---------------------------------------------------------------------------
__global__ void k_dim(const float* __restrict__ W, const float* __restrict__ h,
                      const float* __restrict__ b, float* __restrict__ out) {
    int row = blockIdx.x;
    if (row < D && threadIdx.x == 1) out[row] = 0.f;   // memory_read zero-init
    const float4* w4 = reinterpret_cast<const float4*>(W + (size_t)row * H);
    const float4* h4 = reinterpret_cast<const float4*>(h);
    float s = 0.f;
#pragma unroll 2
    for (int j = threadIdx.x; j < H / 4; j += 256) {
        float4 w = w4[j], x = h4[j];
        s += w.x * x.x + w.y * x.y + w.z * x.z + w.w * x.w;
    }
    __shared__ float red[8];
    s = warp_sum(s);
    if ((threadIdx.x & 31) == 0) red[threadIdx.x >> 5] = s;
    __syncthreads();
    if (threadIdx.x == 0) {
        float v = 0.f;
#pragma unroll
        for (int i = 0; i < 8; i++) v += red[i];
        v += b[row];
        if (row < 5)              g_dim5[row] = v;
        else if (row < 5 + D)     g_k[row - 5] = v;
        else if (row < 5 + 2*D)   g_erase[row - 5 - D] = v;
        else                      g_add[row - 5 - 2*D] = v;
    }
}

// ---------------------------------------------------------------------------
// Fused heavy pass per memory row i:
//   dot(mem_i,k), ||mem_i||^2, ||k||^2 (all from same registers),
//   gate GEMV dot(Wg_i, h)  [streaming loads, evict-first]
//   -> g_s[i] = exp(beta*cos_sim), g_gate[i] = sigmoid.
// <<<N, 256>>>
// ---------------------------------------------------------------------------
__global__ void k_row(const float* __restrict__ mem, const float* __restrict__ Wg,
                      const float* __restrict__ h, const float* __restrict__ bg) {
    int row = blockIdx.x;
    int t = threadIdx.x;
    const float4* m4 = reinterpret_cast<const float4*>(mem + (size_t)row * D);
    const float4* k4 = reinterpret_cast<const float4*>(g_k);
    float d1, d2, d4;
    {
        float4 m = m4[t], kk = k4[t];   // D/4 == 256 == blockDim
        d1 = m.x * kk.x + m.y * kk.y + m.z * kk.z + m.w * kk.w;
        d2 = m.x * m.x + m.y * m.y + m.z * m.z + m.w * m.w;
        d4 = kk.x * kk.x + kk.y * kk.y + kk.z * kk.z + kk.w * kk.w;
    }
    const float4* w4 = reinterpret_cast<const float4*>(Wg + (size_t)row * H);
    const float4* h4 = reinterpret_cast<const float4*>(h);
    float d3 = 0.f;
#pragma unroll 2
    for (int j = t; j < H / 4; j += 256) {
        float4 w = __ldcs(w4 + j);      // stream Wg: keep `memory` in L2
        float4 x = h4[j];
        d3 += w.x * x.x + w.y * x.y + w.z * x.z + w.w * x.w;
    }
    __shared__ float r1[8], r2[8], r3[8], r4[8];
    d1 = warp_sum(d1); d2 = warp_sum(d2); d3 = warp_sum(d3); d4 = warp_sum(d4);
    int w = t >> 5;
    if ((t & 31) == 0) { r1[w] = d1; r2[w] = d2; r3[w] = d3; r4[w] = d4; }
    __syncthreads();
    if (t == 0) {
        float a = 0.f, n2 = 0.f, c = 0.f, k2 = 0.f;
#pragma unroll
        for (int i = 0; i < 8; i++) { a += r1[i]; n2 += r2[i]; c += r3[i]; k2 += r4[i]; }
        float sim = a / (sqrtf(n2) * sqrtf(k2) + EPSV);
        g_s[row] = expf(g_dim5[0] * sim);      // bounded: |beta*sim| small
        float go = c + bg[row];
        g_gate[row] = 1.f / (1.f + expf(-go));
    }
}

// ---------------------------------------------------------------------------
// Shift conv + pow. Each of 64 blocks first reduces the full softmax
// denominator from g_s (L2-hit, 64 loads/thread, deterministic), then
// computes w_tilde^gamma for its 256 indices; writes g_wp and a per-block
// pow-sum partial to g_pp[bid]. <<<64, 256>>>
// ---------------------------------------------------------------------------
__device__ __forceinline__ float wg_at(int j, float inv_sum,
                                       const float* __restrict__ lw) {
    j &= (N - 1);
    float g = g_gate[j];
    return g * g_s[j] * inv_sum + (1.f - g) * lw[j];
}

__global__ void k_shift(const float* __restrict__ lw) {
    int t = threadIdx.x;
    __shared__ float red[8];
    __shared__ float bcast;

    // full softmax-denominator reduce (redundant per block, L2-resident)
    float s = 0.f;
#pragma unroll 4
    for (int j = t; j < N; j += 256) s += g_s[j];
    s = warp_sum(s);
    if ((t & 31) == 0) red[t >> 5] = s;
    __syncthreads();
    if (t == 0) {
        float v = 0.f;
#pragma unroll
        for (int i = 0; i < 8; i++) v += red[i];
        bcast = 1.f / v;
    }
    __syncthreads();
    float inv_sum = bcast;

    float a0 = g_dim5[2], a1 = g_dim5[3], a2 = g_dim5[4];
    float mm = fmaxf(a0, fmaxf(a1, a2));
    float e0 = expf(a0 - mm), e1 = expf(a1 - mm), e2 = expf(a2 - mm);
    float inv3 = 1.f / (e0 + e1 + e2);
    float sh0 = e0 * inv3, sh1 = e1 * inv3, sh2 = e2 * inv3;
    float gamma = g_dim5[1];

    int i = blockIdx.x * 256 + t;
    float wt = sh0 * wg_at(i - 1, inv_sum, lw)
             + sh1 * wg_at(i,     inv_sum, lw)
             + sh2 * wg_at(i + 1, inv_sum, lw);
    float wp = powf(wt, gamma);
    g_wp[i] = wp;

    __syncthreads();
    float p = warp_sum(wp);
    if ((t & 31) == 0) red[t >> 5] = p;
    __syncthreads();
    if (t == 0) {
        float v = 0.f;
#pragma unroll
        for (int i2 = 0; i2 < 8; i2++) v += red[i2];
        g_pp[blockIdx.x] = v;                 // deterministic partial
    }
}

// ---------------------------------------------------------------------------
// new_memory + memory_read + weight output, fused. Reduces g_pp[64] first.
// 1024 blocks x 256 threads; block handles 16 rows; thread owns 1 float4 col.
// `memory` reads should hit L2 (kept resident by streaming hints elsewhere);
// new_memory stores are streaming. <<<N/16, 256>>>
// ---------------------------------------------------------------------------
__global__ void k_update(const float* __restrict__ mem, float* __restrict__ out) {
    int t = threadIdx.x;                       // 0..255 -> cols 4t..4t+3
    __shared__ float red[2];
    __shared__ float bcast;
    // reduce 64 pow-sum partials
    float v = (t < 64) ? g_pp[t] : 0.f;
    v = warp_sum(v);
    if ((t & 31) == 0 && t < 64) red[t >> 5] = v;
    __syncthreads();
    if (t == 0) bcast = 1.f / (red[0] + red[1]);
    __syncthreads();
    float inv = bcast;

    float4* newm = reinterpret_cast<float4*>(out + D + N);
    const float4* m4 = reinterpret_cast<const float4*>(mem);
    float4 e4 = reinterpret_cast<const float4*>(g_erase)[t];
    float4 a4 = reinterpret_cast<const float4*>(g_add)[t];
    float4 acc = make_float4(0.f, 0.f, 0.f, 0.f);
    int base = blockIdx.x * 16;
    if (t < 16) out[D + base + t] = g_wp[base + t] * inv;   // weight output
#pragma unroll 4
    for (int r = 0; r < 16; r++) {
        int row = base + r;
        float w = g_wp[row] * inv;
        float4 m = m4[(size_t)row * 256 + t];
        acc.x += w * m.x; acc.y += w * m.y; acc.z += w * m.z; acc.w += w * m.w;
        float4 nm;
        nm.x = m.x * (1.f - w * e4.x) + w * a4.x;
        nm.y = m.y * (1.f - w * e4.y) + w * a4.y;
        nm.z = m.z * (1.f - w * e4.z) + w * a4.z;
        nm.w = m.w * (1.f - w * e4.w) + w * a4.w;
        __stcs(newm + (size_t)row * 256 + t, nm);   // streaming store
    }
    atomicAdd(&out[4 * t + 0], acc.x);
    atomicAdd(&out[4 * t + 1], acc.y);
    atomicAdd(&out[4 * t + 2], acc.z);
    atomicAdd(&out[4 * t + 3], acc.w);
}

// ---------------------------------------------------------------------------
extern "C" void kernel_launch(void* const* d_in, const int* in_sizes, int n_in,
                              void* d_out, int out_size) {
    const float* hidden = (const float*)d_in[0];
    const float* lw     = (const float*)d_in[1];
    const float* mem    = (const float*)d_in[2];
    const float* Wd     = (const float*)d_in[3];
    const float* bd     = (const float*)d_in[4];
    const float* Wg     = (const float*)d_in[5];
    const float* bg     = (const float*)d_in[6];
    float* out = (float*)d_out;

    k_dim   <<<DIMSZ, 256>>>(Wd, hidden, bd, out);
    k_row   <<<N, 256>>>(mem, Wg, hidden, bg);
    k_shift <<<64, 256>>>(lw);
    k_update<<<N / 16, 256>>>(mem, out);
}

// round 4
// speedup vs baseline: 1.1558x; 1.1558x over previous
#include <cuda_runtime.h>
#include <math.h>

#define H 2048
#define N 16384
#define D 1024
#define EPSV 1e-8f
#define DIMSZ (5 + 3*D)   // 3077
#define UB 512            // k_update blocks
#define RPB (N / UB)      // 32 rows per update block

// ---- scratch (__device__ globals; no allocs allowed) ----
__device__ float g_dim5[5];          // beta, gamma, shift logits
__device__ float g_k[D];
__device__ float g_erase[D];
__device__ float g_add[D];
__device__ float g_s[N];             // exp(beta*sim)  (no max-sub; bounded)
__device__ float g_gate[N];
__device__ float g_wp[N];            // unnormalized w_tilde^gamma
__device__ float g_pp[64];           // per-block pow-sum partials
__device__ float g_part[UB * D];     // per-block memory_read partials (2 MB)

__device__ __forceinline__ float warp_sum(float v) {
#pragma unroll
    for (int o = 16; o; o >>= 1) v += __shfl_xor_sync(0xffffffffu, v, o);
    return v;
}

// ---------------------------------------------------------------------------
// dim_out = W_dim @ hidden + b_dim, scattered into g_dim5/g_k/g_erase/g_add.
// <<<DIMSZ, 256>>>
// ---------------------------------------------------------------------------
__global__ void k_dim(const float* __restrict__ W, const float* __restrict__ h,
                      const float* __restrict__ b) {
    int row = blockIdx.x;
    const float4* w4 = reinterpret_cast<const float4*>(W + (size_t)row * H);
    const float4* h4 = reinterpret_cast<const float4*>(h);
    float s = 0.f;
#pragma unroll 2
    for (int j = threadIdx.x; j < H / 4; j += 256) {
        float4 w = w4[j], x = h4[j];
        s += w.x * x.x + w.y * x.y + w.z * x.z + w.w * x.w;
    }
    __shared__ float red[8];
    s = warp_sum(s);
    if ((threadIdx.x & 31) == 0) red[threadIdx.x >> 5] = s;
    __syncthreads();
    if (threadIdx.x == 0) {
        float v = 0.f;
#pragma unroll
        for (int i = 0; i < 8; i++) v += red[i];
        v += b[row];
        if (row < 5)              g_dim5[row] = v;
        else if (row < 5 + D)     g_k[row - 5] = v;
        else if (row < 5 + 2*D)   g_erase[row - 5 - D] = v;
        else                      g_add[row - 5 - 2*D] = v;
    }
}

// ---------------------------------------------------------------------------
// Fused heavy pass per memory row i:
//   dot(mem_i,k), ||mem_i||^2, ||k||^2 (same registers), gate GEMV
//   -> g_s[i] = exp(beta*cos_sim), g_gate[i] = sigmoid.
// <<<N, 256>>>
// ---------------------------------------------------------------------------
__global__ void k_row(const float* __restrict__ mem, const float* __restrict__ Wg,
                      const float* __restrict__ h, const float* __restrict__ bg) {
    int row = blockIdx.x;
    int t = threadIdx.x;
    const float4* m4 = reinterpret_cast<const float4*>(mem + (size_t)row * D);
    const float4* k4 = reinterpret_cast<const float4*>(g_k);
    const float4* w4 = reinterpret_cast<const float4*>(Wg + (size_t)row * H);
    const float4* h4 = reinterpret_cast<const float4*>(h);
    // batch all loads up front: m, k, wg0, wg1, h0, h1
    float4 m  = m4[t];
    float4 kk = k4[t];
    float4 w0 = w4[t], w1 = w4[t + 256];
    float4 x0 = h4[t], x1 = h4[t + 256];
    float d1 = m.x * kk.x + m.y * kk.y + m.z * kk.z + m.w * kk.w;
    float d2 = m.x * m.x + m.y * m.y + m.z * m.z + m.w * m.w;
    float d4 = kk.x * kk.x + kk.y * kk.y + kk.z * kk.z + kk.w * kk.w;
    float d3 = w0.x * x0.x + w0.y * x0.y + w0.z * x0.z + w0.w * x0.w
             + w1.x * x1.x + w1.y * x1.y + w1.z * x1.z + w1.w * x1.w;

    __shared__ float r1[8], r2[8], r3[8], r4[8];
    d1 = warp_sum(d1); d2 = warp_sum(d2); d3 = warp_sum(d3); d4 = warp_sum(d4);
    int w = t >> 5;
    if ((t & 31) == 0) { r1[w] = d1; r2[w] = d2; r3[w] = d3; r4[w] = d4; }
    __syncthreads();
    if (t == 0) {
        float a = 0.f, n2 = 0.f, c = 0.f, k2 = 0.f;
#pragma unroll
        for (int i = 0; i < 8; i++) { a += r1[i]; n2 += r2[i]; c += r3[i]; k2 += r4[i]; }
        float sim = a / (sqrtf(n2) * sqrtf(k2) + EPSV);
        g_s[row] = expf(g_dim5[0] * sim);      // bounded: |beta*sim| small
        float go = c + bg[row];
        g_gate[row] = 1.f / (1.f + expf(-go));
    }
}

// ---------------------------------------------------------------------------
// Shift conv + pow. Each of 64 blocks reduces the full softmax denominator
// (L2-resident, deterministic), then computes w_tilde^gamma for its 256
// indices; writes g_wp and a per-block pow-sum partial. <<<64, 256>>>
// ---------------------------------------------------------------------------
__device__ __forceinline__ float wg_at(int j, float inv_sum,
                                       const float* __restrict__ lw) {
    j &= (N - 1);
    float g = g_gate[j];
    return g * g_s[j] * inv_sum + (1.f - g) * lw[j];
}

__global__ void k_shift(const float* __restrict__ lw) {
    int t = threadIdx.x;
    __shared__ float red[8];
    __shared__ float bcast;

    float s = 0.f;
#pragma unroll 8
    for (int j = t; j < N; j += 256) s += g_s[j];
    s = warp_sum(s);
    if ((t & 31) == 0) red[t >> 5] = s;
    __syncthreads();
    if (t == 0) {
        float v = 0.f;
#pragma unroll
        for (int i = 0; i < 8; i++) v += red[i];
        bcast = 1.f / v;
    }
    __syncthreads();
    float inv_sum = bcast;

    float a0 = g_dim5[2], a1 = g_dim5[3], a2 = g_dim5[4];
    float mm = fmaxf(a0, fmaxf(a1, a2));
    float e0 = expf(a0 - mm), e1 = expf(a1 - mm), e2 = expf(a2 - mm);
    float inv3 = 1.f / (e0 + e1 + e2);
    float sh0 = e0 * inv3, sh1 = e1 * inv3, sh2 = e2 * inv3;
    float gamma = g_dim5[1];

    int i = blockIdx.x * 256 + t;
    float wt = sh0 * wg_at(i - 1, inv_sum, lw)
             + sh1 * wg_at(i,     inv_sum, lw)
             + sh2 * wg_at(i + 1, inv_sum, lw);
    float wp = powf(wt, gamma);
    g_wp[i] = wp;

    __syncthreads();
    float p = warp_sum(wp);
    if ((t & 31) == 0) red[t >> 5] = p;
    __syncthreads();
    if (t == 0) {
        float v = 0.f;
#pragma unroll
        for (int i2 = 0; i2 < 8; i2++) v += red[i2];
        g_pp[blockIdx.x] = v;                 // deterministic partial
    }
}

// ---------------------------------------------------------------------------
// new_memory + weight output + memory_read PARTIALS (no atomics).
// 512 blocks x 256 threads; block handles 32 rows; thread owns 1 float4 col.
// All w values preloaded to smem; m loads batched 8 rows deep (MLP_p1=8).
// <<<UB, 256>>>
// ---------------------------------------------------------------------------
__global__ void __launch_bounds__(256) k_update(const float* __restrict__ mem,
                                                float* __restrict__ out) {
    int t = threadIdx.x;                       // 0..255 -> cols 4t..4t+3
    __shared__ float red2[2];
    __shared__ float w_s[RPB];
    // reduce 64 pow-sum partials -> inv
    float v = (t < 64) ? g_pp[t] : 0.f;
    v = warp_sum(v);
    if ((t & 31) == 0 && t < 64) red2[t >> 5] = v;
    __syncthreads();
    if (t == 0) red2[0] = 1.f / (red2[0] + red2[1]);
    __syncthreads();
    float inv = red2[0];

    int base = blockIdx.x * RPB;
    if (t < RPB) {
        float wv = g_wp[base + t] * inv;
        w_s[t] = wv;
        out[D + base + t] = wv;                // weight output
    }
    __syncthreads();

    float4* newm = reinterpret_cast<float4*>(out + D + N);
    const float4* m4 = reinterpret_cast<const float4*>(mem);
    float4 e4 = reinterpret_cast<const float4*>(g_erase)[t];
    float4 a4 = reinterpret_cast<const float4*>(g_add)[t];
    float4 acc = make_float4(0.f, 0.f, 0.f, 0.f);

#pragma unroll
    for (int r0 = 0; r0 < RPB; r0 += 8) {
        float4 m[8];
#pragma unroll
        for (int u = 0; u < 8; u++)
            m[u] = m4[(size_t)(base + r0 + u) * 256 + t];
#pragma unroll
        for (int u = 0; u < 8; u++) {
            float w = w_s[r0 + u];
            acc.x += w * m[u].x; acc.y += w * m[u].y;
            acc.z += w * m[u].z; acc.w += w * m[u].w;
            float4 nm;
            nm.x = m[u].x * (1.f - w * e4.x) + w * a4.x;
            nm.y = m[u].y * (1.f - w * e4.y) + w * a4.y;
            nm.z = m[u].z * (1.f - w * e4.z) + w * a4.z;
            nm.w = m[u].w * (1.f - w * e4.w) + w * a4.w;
            newm[(size_t)(base + r0 + u) * 256 + t] = nm;
        }
    }
    reinterpret_cast<float4*>(g_part + (size_t)blockIdx.x * D)[t] = acc;
}

// ---------------------------------------------------------------------------
// Fold UB partials per column into memory_read. <<<D/256, 256>>>
// ---------------------------------------------------------------------------
__global__ void k_read(float* __restrict__ out) {
    int col = blockIdx.x * 256 + threadIdx.x;
    float s = 0.f;
#pragma unroll 8
    for (int b = 0; b < UB; b++) s += g_part[(size_t)b * D + col];
    out[col] = s;
}

// ---------------------------------------------------------------------------
extern "C" void kernel_launch(void* const* d_in, const int* in_sizes, int n_in,
                              void* d_out, int out_size) {
    const float* hidden = (const float*)d_in[0];
    const float* lw     = (const float*)d_in[1];
    const float* mem    = (const float*)d_in[2];
    const float* Wd     = (const float*)d_in[3];
    const float* bd     = (const float*)d_in[4];
    const float* Wg     = (const float*)d_in[5];
    const float* bg     = (const float*)d_in[6];
    float* out = (float*)d_out;

    k_dim   <<<DIMSZ, 256>>>(Wd, hidden, bd);
    k_row   <<<N, 256>>>(mem, Wg, hidden, bg);
    k_shift <<<64, 256>>>(lw);
    k_update<<<UB, 256>>>(mem, out);
    k_read  <<<D / 256, 256>>>(out);
}